// round 14
// baseline (speedup 1.0000x reference)
#include <cuda_runtime.h>
#include <cuda_bf16.h>
#include <cuda_fp16.h>
#include <cstdint>

// ---------------------------------------------------------------------------
// HungarianMatcher cost matrix. B=16 Q=900 C=91 T=4800, out [14400,4800] f32.
//
// R14 = R13 (best, 93.9us) + I-cache + pipe-pressure polish:
//  - quad loop NOT unrolled (#pragma unroll 1): hot body ~370 instr ~ 5.9KB
//    fits L0 I$ (6KB); full unroll was ~24KB streaming from L1.5 (+~3%)
//  - gather prefetch made branch-free: g_Fh padded by one quad block so the
//    depth-1 prefetch may harmlessly read one quad past the last row-block
//  - FFMA-imm (rt=1, 2x tput vs FADD rt=2) for the abs-free adds: asum, uni,
//    and the f2+bx accumulation, locked via inline asm fma.rn with imm 1.0
//  - unchanged: fp16 quad-interleaved focal, f32x2 packed giou (R13),
//    uni^2 single-rcp tail, streaming stores, merged prep, exact tiling
// ---------------------------------------------------------------------------

#define BQ_MAX   14400
#define T_MAX    4800
#define NCLS     91
#define CP       96            // class stride; fp16 quad block = 4*CP*2 = 768B

// padded by one quad block (4*CP halves) so depth-1 prefetch never reads OOB
__device__ __align__(128) __half g_Fh[BQ_MAX * CP + 4 * CP];
__device__ float4 g_tgtA[T_MAX];        // -5*cxcywh  (negated)
__device__ float4 g_tgtB[T_MAX];        // {x0, y0, -x1, -y1}
__device__ float4 g_tgtE[T_MAX];        // {w, h, area, asfloat(cls*8)}
__device__ float4 g_rowA[BQ_MAX];       // +5*cxcywh
__device__ float4 g_rowB[BQ_MAX];       // {x0, y0, -x1, -y1}
__device__ float4 g_rowE[BQ_MAX];       // {w, h, area, 0}

__device__ __forceinline__ float frcp_approx(float x) {
    float r;
    asm("rcp.approx.f32 %0, %1;" : "=f"(r) : "f"(x));
    return r;
}

#define ADD_F32X2(out, a, b) \
    asm("add.rn.f32x2 %0, %1, %2;" : "=l"(out) : "l"(a), "l"(b))
#define UNPACK2F(lo, hi, in) \
    asm("mov.b64 {%0, %1}, %2;" : "=f"(lo), "=f"(hi) : "l"(in))
#define PACK2F(out, lo, hi) \
    asm("mov.b64 %0, {%1, %2};" : "=l"(out) : "f"(lo), "f"(hi))
// FFMA with immediate multiplier: rt_SMSP = 1 (vs FADD rt = 2)
#define FFMA_P1(d, a, c) \
    asm("fma.rn.f32 %0, %1, 0f3F800000, %2;" : "=f"(d) : "f"(a), "f"(c))
#define FFMA_N1(d, a, c) \
    asm("fma.rn.f32 %0, %1, 0fBF800000, %2;" : "=f"(d) : "f"(a), "f"(c))

// --------------------- merged prep (single launch) --------------------------
__global__ void prep_all(const float* __restrict__ logits,
                         const float* __restrict__ pboxes,
                         const float* __restrict__ tboxes,
                         const int*   __restrict__ ids,
                         int BQ, int C, int T) {
    int i = blockIdx.x * blockDim.x + threadIdx.x;

    if (i < BQ * C) {
        int row = i / C;
        int c   = i - row * C;
        float x = logits[i];
        float e = __expf(-x);
        float inv = frcp_approx(1.0f + e);
        float p = inv;          // sigmoid
        float q = e * inv;      // 1 - sigmoid, no cancellation
        float lp = __logf(p + 1e-8f);
        float lq = __logf(q + 1e-8f);
        // 2*(pos-neg) + 2   (the +2 from the uni^2 giou rewrite)
        float F2 = -0.5f * q * q * lp + 1.5f * p * p * lq + 2.0f;
        g_Fh[(row >> 2) * (4 * CP) + c * 4 + (row & 3)] = __float2half_rn(F2);
    }

    if (i < BQ) {
        float4 b = reinterpret_cast<const float4*>(pboxes)[i];  // cx,cy,w,h
        g_rowA[i] = make_float4(5.f*b.x, 5.f*b.y, 5.f*b.z, 5.f*b.w);
        float x0 = b.x - 0.5f*b.z, y0 = b.y - 0.5f*b.w;
        float x1 = b.x + 0.5f*b.z, y1 = b.y + 0.5f*b.w;
        float w = x1 - x0, h = y1 - y0;
        g_rowB[i] = make_float4(x0, y0, -x1, -y1);
        g_rowE[i] = make_float4(w, h, w * h, 0.f);
    }

    if (i < T) {
        float4 b = reinterpret_cast<const float4*>(tboxes)[i];
        g_tgtA[i] = make_float4(-5.f*b.x, -5.f*b.y, -5.f*b.z, -5.f*b.w);
        float x0 = b.x - 0.5f*b.z, y0 = b.y - 0.5f*b.w;
        float x1 = b.x + 0.5f*b.z, y1 = b.y + 0.5f*b.w;
        float w = x1 - x0, h = y1 - y0;
        g_tgtB[i] = make_float4(x0, y0, -x1, -y1);
        // class byte offset within an fp16 quad block: cls * 8
        g_tgtE[i] = make_float4(w, h, w * h, __int_as_float((ids[i] - 1) * 8));
    }
}

// ---------------------------- main kernel -----------------------------------
// Block 256 threads = 64 rows x 192 targets (4800 = 25*192, 14400 = 225*64).
//   rr = tid>>6 -> rows row0 + rr*16 (four quads); tt = tid&63 -> 3 targets
#define ROW_TILE 64
#define TGT_TILE 192
#define RPT      16
#define QSTRIDE  (4 * CP * 2)   // bytes between consecutive row-quads

__global__ void __launch_bounds__(256, 3)
cost_kernel(float* __restrict__ out, int T) {
    const int tid  = threadIdx.x;
    const int tt   = tid & 63;
    const int rr   = tid >> 6;
    const int row0 = blockIdx.y * ROW_TILE + rr * RPT;   // multiple of 16
    const int base = blockIdx.x * TGT_TILE + tt;

    // ---- 3 targets in registers (coalesced loads) ----
    unsigned long long taL[3], taH[3];     // packed (-5cx,-5cy) / (-5w,-5h)
    float4 tb[3];
    unsigned long long tE_wh[3];           // packed (wt, ht)
    float  tarea[3];
    const char* qp_ptr[3];                 // running gather pointers
    {
        const int qbase = (row0 >> 2) * QSTRIDE;
        const char* fbase = reinterpret_cast<const char*>(g_Fh);
        #pragma unroll
        for (int k = 0; k < 3; ++k) {
            const int j = base + (k << 6);
            ulonglong2 a = *reinterpret_cast<const ulonglong2*>(&g_tgtA[j]);
            taL[k] = a.x;  taH[k] = a.y;
            tb[k]  = g_tgtB[j];
            ulonglong2 e = *reinterpret_cast<const ulonglong2*>(&g_tgtE[j]);
            tE_wh[k] = e.x;                            // (w, h) packed
            float2 ez = *reinterpret_cast<const float2*>(&e.y);
            tarea[k] = ez.x;
            qp_ptr[k] = fbase + (qbase + __float_as_int(ez.y));
        }
    }

    float* dstRow = out + (size_t)row0 * T + base;

    // depth-1 pipelined gathers (branch-free: g_Fh is padded by one quad)
    uint2 raw[3];
    #pragma unroll
    for (int k = 0; k < 3; ++k)
        raw[k] = __ldg(reinterpret_cast<const uint2*>(qp_ptr[k]));

    int rowCur = row0;

    #pragma unroll 1                       // keep hot body inside L0 I$
    for (int qp = 0; qp < RPT / 4; ++qp) {
        uint2 nxt[3];
        #pragma unroll
        for (int k = 0; k < 3; ++k) {
            qp_ptr[k] += QSTRIDE;
            nxt[k] = __ldg(reinterpret_cast<const uint2*>(qp_ptr[k]));
        }

        // convert current quad's fp16 focal values (contain focal*2 + 2)
        float4 f4[3];
        #pragma unroll
        for (int k = 0; k < 3; ++k) {
            float2 lo = __half22float2(*reinterpret_cast<__half2*>(&raw[k].x));
            float2 hi = __half22float2(*reinterpret_cast<__half2*>(&raw[k].y));
            f4[k] = make_float4(lo.x, lo.y, hi.x, hi.y);
        }

        #pragma unroll
        for (int r4 = 0; r4 < 4; ++r4) {
            const int row = rowCur + r4;
            // warp-uniform row loads (broadcast, 1 wavefront each)
            const ulonglong2 rA2 =
                *reinterpret_cast<const ulonglong2*>(&g_rowA[row]);
            const float4 rB = g_rowB[row];       // {x0, y0, -x1, -y1}
            const ulonglong2 rE2 =
                *reinterpret_cast<const ulonglong2*>(&g_rowE[row]);
            const float rarea =
                reinterpret_cast<const float2*>(&rE2.y)->x;

            #pragma unroll
            for (int k = 0; k < 3; ++k) {
                const float f2 = reinterpret_cast<const float*>(&f4[k])[r4];

                // ---- 5*L1: packed diffs (rA=+5c, ta=-5c) ----
                unsigned long long dxy, dzw;
                ADD_F32X2(dxy, rA2.x, taL[k]);
                ADD_F32X2(dzw, rA2.y, taH[k]);
                float d0, d1, d2, d3;
                UNPACK2F(d0, d1, dxy);
                UNPACK2F(d2, d3, dzw);
                float s1 = fabsf(d0) + fabsf(d1);
                float s2 = fabsf(d2) + fabsf(d3);
                float s3, sfb;
                FFMA_P1(s3, s1, f2);          // s3 = s1 + f2   (FFMA-imm rt1)
                FFMA_P1(sfb, s2, s3);         // sfb = f2 + bx

                // ---- intersection via negated-sw form ----
                float Mx = fmaxf(rB.x, tb[k].x);     // max(x0)
                float My = fmaxf(rB.y, tb[k].y);     // max(y0)
                float Nx = fmaxf(rB.z, tb[k].z);     // max(-x1) = -min(x1)
                float Ny = fmaxf(rB.w, tb[k].w);
                unsigned long long Mxy, Nxy, nswh;
                PACK2F(Mxy, Mx, My);
                PACK2F(Nxy, Nx, Ny);
                ADD_F32X2(nswh, Mxy, Nxy);           // (-sw, -sh)
                float nsw, nsh;
                UNPACK2F(nsw, nsh, nswh);
                float niw = fminf(nsw, 0.0f);        // = -iw
                float nih = fminf(nsh, 0.0f);        // = -ih
                float inter = niw * nih;             // iw*ih

                // ---- enclosing, packed: encwh = (wr+wt) + (-sw,-sh) ----
                unsigned long long wsum, encwh;
                ADD_F32X2(wsum, rE2.x, tE_wh[k]);    // (wr+wt, hr+ht)
                ADD_F32X2(encwh, wsum, nswh);
                float encw, ench;
                UNPACK2F(encw, ench, encwh);
                float enc = encw * ench;

                // uni >= max(area_r, area_t) > 0: no clamps needed
                float asum, uni;
                FFMA_P1(asum, tarea[k], rarea);      // asum = rarea + tarea
                FFMA_N1(uni, inter, asum);           // uni  = asum - inter

                // -2*giou = 2 - 2*(inter*enc + uni^2)/(uni*enc); +2 in f2
                float num = fmaf(uni, uni, inter * enc);
                float inv = frcp_approx(uni * enc);

                float res = fmaf(num * inv, -2.0f, sfb);
                __stcs(dstRow + (k << 6), res);      // STG.CS, coalesced
            }
            dstRow += T;   // walk rows (single IADD)
        }
        rowCur += 4;

        #pragma unroll
        for (int k = 0; k < 3; ++k) raw[k] = nxt[k];
    }
}

// ---------------------------------------------------------------------------
extern "C" void kernel_launch(void* const* d_in, const int* in_sizes, int n_in,
                              void* d_out, int out_size) {
    const float* pred_logits = (const float*)d_in[0];
    const float* pred_boxes  = (const float*)d_in[1];
    const int*   tgt_ids     = (const int*)d_in[2];
    const float* tgt_boxes   = (const float*)d_in[3];
    float* out = (float*)d_out;

    const int BQ = in_sizes[1] / 4;          // 14400
    const int C  = in_sizes[0] / BQ;         // 91
    const int T  = in_sizes[2];              // 4800

    prep_all<<<(BQ * C + 255) / 256, 256>>>(pred_logits, pred_boxes,
                                            tgt_boxes, tgt_ids, BQ, C, T);

    // exact tiling: 4800 = 25*192, 14400 = 225*64
    dim3 grid(T / TGT_TILE, BQ / ROW_TILE);
    cost_kernel<<<grid, 256>>>(out, T);
}